// round 1
// baseline (speedup 1.0000x reference)
#include <cuda_runtime.h>
#include <math.h>

#define MTOK 32768
#define DD   1152
#define HH   4608

// ---------------- scratch (static device globals; no runtime alloc) ----------------
__device__ float g_qx[(size_t)MTOK * DD];      // quantized x as float(int8 value)
__device__ float g_xscale[MTOK];
__device__ float g_w1hi[(size_t)HH * DD];
__device__ float g_w1lo[(size_t)HH * DD];
__device__ float g_w2hi[(size_t)DD * HH];
__device__ float g_h[(size_t)MTOK * HH];       // post-GELU h, then overwritten with q
__device__ float g_hscale[MTOK];

// ---------------- helpers ----------------
__device__ __forceinline__ float gelu_exact(float v) {
    return 0.5f * v * (1.0f + erff(v * 0.70710678118654752440f));
}

__device__ __forceinline__ void cpa16(float* s, const float* g) {
    unsigned sa = (unsigned)__cvta_generic_to_shared(s);
    asm volatile("cp.async.cg.shared.global [%0], [%1], 16;\n" :: "r"(sa), "l"(g));
}
__device__ __forceinline__ void cpcommit() { asm volatile("cp.async.commit_group;\n"); }
__device__ __forceinline__ void cpwait0()  { asm volatile("cp.async.wait_group 0;\n"); }

__device__ __forceinline__ void mma_tf32(float* d, const float* a, float b0, float b1) {
    asm volatile(
        "mma.sync.aligned.m16n8k8.row.col.f32.tf32.tf32.f32 "
        "{%0,%1,%2,%3}, {%4,%5,%6,%7}, {%8,%9}, {%0,%1,%2,%3};\n"
        : "+f"(d[0]), "+f"(d[1]), "+f"(d[2]), "+f"(d[3])
        : "r"(__float_as_uint(a[0])), "r"(__float_as_uint(a[1])),
          "r"(__float_as_uint(a[2])), "r"(__float_as_uint(a[3])),
          "r"(__float_as_uint(b0)),  "r"(__float_as_uint(b1)));
}

__device__ __forceinline__ float to_tf32_rna(float w) {
    unsigned u;
    asm("cvt.rna.tf32.f32 %0, %1;" : "=r"(u) : "f"(w));
    return __uint_as_float(u);
}

// ---------------- weight preparation: W1 -> tf32 hi+lo, W2 -> tf32 hi ----------------
__global__ void prep_w_kernel(const float* __restrict__ W1, const float* __restrict__ W2,
                              float* __restrict__ w1hi, float* __restrict__ w1lo,
                              float* __restrict__ w2hi) {
    int i = blockIdx.x * 256 + threadIdx.x;
    if (i < HH * DD) {
        float w  = W1[i];
        float hi = to_tf32_rna(w);
        float lo = to_tf32_rna(w - hi);
        w1hi[i] = hi;
        w1lo[i] = lo;
        w2hi[i] = to_tf32_rna(W2[i]);
    }
}

// ---------------- quant of x (with channel reorder) ----------------
__global__ void quant_x_kernel(const float* __restrict__ x, const int* __restrict__ ridx,
                               float* __restrict__ qx, float* __restrict__ xs) {
    __shared__ float sv[DD];
    __shared__ float red[9];
    int m = blockIdx.x;
    int tid = threadIdx.x;
    const float* row = x + (size_t)m * DD;

    float mx = 0.0f;
    for (int d = tid; d < DD; d += 256) {
        float v = row[ridx[d]];
        sv[d] = v;
        mx = fmaxf(mx, fabsf(v));
    }
    #pragma unroll
    for (int o = 16; o > 0; o >>= 1) mx = fmaxf(mx, __shfl_xor_sync(0xffffffffu, mx, o));
    if ((tid & 31) == 0) red[tid >> 5] = mx;
    __syncthreads();
    if (tid == 0) {
        float t = red[0];
        #pragma unroll
        for (int i = 1; i < 8; i++) t = fmaxf(t, red[i]);
        red[8] = fmaxf(__fdiv_rn(t, 127.0f), 1e-8f);
    }
    __syncthreads();
    float scale = red[8];
    for (int d = tid; d < DD; d += 256) {
        float q = rintf(__fdiv_rn(sv[d], scale));
        q = fminf(fmaxf(q, -128.0f), 127.0f);
        qx[(size_t)m * DD + d] = q;
    }
    if (tid == 0) xs[m] = scale;
}

// ---------------- quant of h (in place) ----------------
__global__ void quant_h_kernel(float* __restrict__ h, float* __restrict__ hs) {
    __shared__ float sv[HH];
    __shared__ float red[9];
    int m = blockIdx.x;
    int tid = threadIdx.x;
    float* row = h + (size_t)m * HH;

    float mx = 0.0f;
    for (int d = tid; d < HH; d += 256) {
        float v = row[d];
        sv[d] = v;
        mx = fmaxf(mx, fabsf(v));
    }
    #pragma unroll
    for (int o = 16; o > 0; o >>= 1) mx = fmaxf(mx, __shfl_xor_sync(0xffffffffu, mx, o));
    if ((tid & 31) == 0) red[tid >> 5] = mx;
    __syncthreads();
    if (tid == 0) {
        float t = red[0];
        #pragma unroll
        for (int i = 1; i < 8; i++) t = fmaxf(t, red[i]);
        red[8] = fmaxf(__fdiv_rn(t, 127.0f), 1e-8f);
    }
    __syncthreads();
    float scale = red[8];
    for (int d = tid; d < HH; d += 256) {
        float q = rintf(__fdiv_rn(sv[d], scale));
        q = fminf(fmaxf(q, -128.0f), 127.0f);
        row[d] = q;
    }
    if (tid == 0) hs[m] = scale;
}

// ---------------- tf32 GEMM: C = op(rowscale[m] * (A @ (B0+B1)^T) + bias[n]) ----------------
// A: [M,K] row-major (float q values).  B0/B1: [N,K] row-major (tf32-rounded).
// NB=2 accumulates both B0 and B1 into the same accumulator (hi+lo split).
// DO_GELU applies exact GELU in the epilogue.
// CTA tile 128x128, KT=16, 8 warps (4x2), warp tile 32x64, double-buffered cp.async.
#define SST 20  // smem row stride (floats): keeps 16B alignment, conflict-free frag LDS

template<int NB, bool DO_GELU>
__global__ __launch_bounds__(256, 2)
void gemm_tf32(const float* __restrict__ A, const float* __restrict__ B0,
               const float* __restrict__ B1, const float* __restrict__ rs,
               const float* __restrict__ bias, float* __restrict__ C,
               int M, int N, int K) {
    extern __shared__ float sm[];
    const int tid  = threadIdx.x;
    const int m0   = blockIdx.y * 128;
    const int n0   = blockIdx.x * 128;
    const int lane = tid & 31, warp = tid >> 5;
    const int wm = warp >> 1, wn = warp & 1;
    const int g  = lane >> 2, t4 = lane & 3;

    const int ASZ = 128 * SST;        // floats per A stage
    const int BSZ = NB * 128 * SST;   // floats per B stage

    float acc[2][8][4];
    #pragma unroll
    for (int mt = 0; mt < 2; mt++)
        #pragma unroll
        for (int nt = 0; nt < 8; nt++)
            #pragma unroll
            for (int i = 0; i < 4; i++) acc[mt][nt][i] = 0.0f;

    const float* Ag = A + (size_t)m0 * K;

    auto load_stage = [&](int kt, int st) {
        int k0 = kt * 16;
        #pragma unroll
        for (int i = 0; i < 2; i++) {
            int idx = tid + i * 256;
            int r = idx >> 2;
            int c = (idx & 3) << 2;
            cpa16(&sm[st * ASZ + r * SST + c], Ag + (size_t)r * K + k0 + c);
        }
        #pragma unroll
        for (int nb = 0; nb < NB; nb++) {
            const float* Bg = (nb ? B1 : B0) + (size_t)n0 * K;
            #pragma unroll
            for (int i = 0; i < 2; i++) {
                int idx = tid + i * 256;
                int r = idx >> 2;
                int c = (idx & 3) << 2;
                cpa16(&sm[2 * ASZ + st * BSZ + (nb * 128 + r) * SST + c],
                      Bg + (size_t)r * K + k0 + c);
            }
        }
    };

    auto compute_stage = [&](int st) {
        const float* As = sm + st * ASZ;
        const float* Bs = sm + 2 * ASZ + st * BSZ;
        #pragma unroll
        for (int ks = 0; ks < 2; ks++) {
            float a[2][4];
            #pragma unroll
            for (int mt = 0; mt < 2; mt++) {
                int r = wm * 32 + mt * 16 + g;
                int c = ks * 8 + t4;
                a[mt][0] = As[r * SST + c];
                a[mt][1] = As[(r + 8) * SST + c];
                a[mt][2] = As[r * SST + c + 4];
                a[mt][3] = As[(r + 8) * SST + c + 4];
            }
            #pragma unroll
            for (int nb = 0; nb < NB; nb++) {
                #pragma unroll
                for (int nt = 0; nt < 8; nt++) {
                    int rb = nb * 128 + wn * 64 + nt * 8 + g;
                    float b0 = Bs[rb * SST + ks * 8 + t4];
                    float b1 = Bs[rb * SST + ks * 8 + t4 + 4];
                    mma_tf32(acc[0][nt], a[0], b0, b1);
                    mma_tf32(acc[1][nt], a[1], b0, b1);
                }
            }
        }
    };

    const int nkt = K / 16;
    load_stage(0, 0);
    cpcommit();
    cpwait0();
    __syncthreads();

    for (int kt = 0; kt < nkt; kt++) {
        int cur = kt & 1;
        if (kt + 1 < nkt) { load_stage(kt + 1, cur ^ 1); cpcommit(); }
        compute_stage(cur);
        cpwait0();
        __syncthreads();
    }

    // epilogue
    #pragma unroll
    for (int mt = 0; mt < 2; mt++) {
        int r0 = m0 + wm * 32 + mt * 16 + g;
        float s0 = rs[r0], s1 = rs[r0 + 8];
        #pragma unroll
        for (int nt = 0; nt < 8; nt++) {
            int c0 = n0 + wn * 64 + nt * 8 + (t4 << 1);
            float bb0 = bias[c0], bb1 = bias[c0 + 1];
            float v00 = acc[mt][nt][0] * s0 + bb0;
            float v01 = acc[mt][nt][1] * s0 + bb1;
            float v10 = acc[mt][nt][2] * s1 + bb0;
            float v11 = acc[mt][nt][3] * s1 + bb1;
            if (DO_GELU) {
                v00 = gelu_exact(v00); v01 = gelu_exact(v01);
                v10 = gelu_exact(v10); v11 = gelu_exact(v11);
            }
            *(float2*)&C[(size_t)r0 * N + c0]       = make_float2(v00, v01);
            *(float2*)&C[(size_t)(r0 + 8) * N + c0] = make_float2(v10, v11);
        }
    }
}

// ---------------- launch ----------------
extern "C" void kernel_launch(void* const* d_in, const int* in_sizes, int n_in,
                              void* d_out, int out_size) {
    const float* x    = (const float*)d_in[0];
    const int*   ridx = (const int*)  d_in[1];
    const float* W1   = (const float*)d_in[2];
    const float* b1   = (const float*)d_in[3];
    const float* W2   = (const float*)d_in[4];
    const float* b2   = (const float*)d_in[5];
    float* out = (float*)d_out;
    (void)in_sizes; (void)n_in; (void)out_size;

    void* p;
    float *qx, *xs, *w1hi, *w1lo, *w2hi, *hbuf, *hs;
    cudaGetSymbolAddress(&p, g_qx);     qx   = (float*)p;
    cudaGetSymbolAddress(&p, g_xscale); xs   = (float*)p;
    cudaGetSymbolAddress(&p, g_w1hi);   w1hi = (float*)p;
    cudaGetSymbolAddress(&p, g_w1lo);   w1lo = (float*)p;
    cudaGetSymbolAddress(&p, g_w2hi);   w2hi = (float*)p;
    cudaGetSymbolAddress(&p, g_h);      hbuf = (float*)p;
    cudaGetSymbolAddress(&p, g_hscale); hs   = (float*)p;

    const int smem1 = (2 * 128 * SST + 2 * 2 * 128 * SST) * 4;  // 61440 B
    const int smem2 = (2 * 128 * SST + 2 * 1 * 128 * SST) * 4;  // 40960 B
    cudaFuncSetAttribute(gemm_tf32<2, true>,  cudaFuncAttributeMaxDynamicSharedMemorySize, smem1);
    cudaFuncSetAttribute(gemm_tf32<1, false>, cudaFuncAttributeMaxDynamicSharedMemorySize, smem2);

    prep_w_kernel<<<(HH * DD + 255) / 256, 256>>>(W1, W2, w1hi, w1lo, w2hi);
    quant_x_kernel<<<MTOK, 256>>>(x, ridx, qx, xs);
    gemm_tf32<2, true><<<dim3(HH / 128, MTOK / 128), 256, smem1>>>(
        qx, w1hi, w1lo, xs, b1, hbuf, MTOK, HH, DD);
    quant_h_kernel<<<MTOK, 256>>>(hbuf, hs);
    gemm_tf32<1, false><<<dim3(DD / 128, MTOK / 128), 256, smem2>>>(
        hbuf, w2hi, nullptr, hs, b2, out, MTOK, DD, HH);
}